// round 2
// baseline (speedup 1.0000x reference)
#include <cuda_runtime.h>
#include <cuda_bf16.h>

// ---------------------------------------------------------------------------
// GraphBackboneGCN: 3x (GCNConv + ReLU) + global mean pool.
//   N = 50000 nodes, E = 800000 edges, D = H = 128, 512 graphs.
//   edge_index / batch arrive as int32 (harness dtype set: f32/i32/bf16).
// ---------------------------------------------------------------------------

#define NMAX 50176
#define EMAX 1048576
#define D 128
#define NGRAPH 512

__device__ __align__(128) float g_h1[(size_t)NMAX * D];   // layer output
__device__ __align__(128) float g_h2[(size_t)NMAX * D];   // gemm tmp
__device__ float g_dinv[NMAX];
__device__ int   g_cnt[NMAX];          // per-dst edge count, then fill cursor
__device__ int   g_off[NMAX + 1];      // CSR row offsets
__device__ int   g_csr_src[EMAX];
__device__ __align__(128) float g_csr_coef[EMAX];
__device__ float g_gcnt[NGRAPH];

// ---------------------------------------------------------------------------
// init: zero counters, graph counts, and the output buffer
__global__ void k_init(float* __restrict__ out, int N) {
    int i = blockIdx.x * blockDim.x + threadIdx.x;
    if (i < N) g_cnt[i] = 0;
    if (i < NGRAPH) g_gcnt[i] = 0.f;
    if (i < NGRAPH * D) out[i] = 0.f;
}

// count in-degree per dst
__global__ void k_count(const int* __restrict__ dst, int E) {
    int e = blockIdx.x * blockDim.x + threadIdx.x;
    if (e < E) atomicAdd(&g_cnt[dst[e]], 1);
}

// dinv = (deg+1)^-0.5   (the +1 is the self-loop)
__global__ void k_dinv(int N) {
    int i = blockIdx.x * blockDim.x + threadIdx.x;
    if (i < N) g_dinv[i] = rsqrtf((float)(g_cnt[i] + 1));
}

// single-block exclusive scan of g_cnt -> g_off, zeroing g_cnt for reuse
__global__ void k_scan(int N) {
    __shared__ int s[1024];
    __shared__ int carry_s;
    int tid = threadIdx.x;
    if (tid == 0) carry_s = 0;
    __syncthreads();
    for (int base = 0; base < N; base += 1024) {
        int i = base + tid;
        int v = (i < N) ? g_cnt[i] : 0;
        if (i < N) g_cnt[i] = 0;
        s[tid] = v;
        __syncthreads();
        for (int d2 = 1; d2 < 1024; d2 <<= 1) {
            int t = (tid >= d2) ? s[tid - d2] : 0;
            __syncthreads();
            s[tid] += t;
            __syncthreads();
        }
        if (i < N) g_off[i] = carry_s + s[tid] - v;   // exclusive
        __syncthreads();
        if (tid == 1023) carry_s += s[1023];
        __syncthreads();
    }
    if (tid == 0) g_off[N] = carry_s;
}

// scatter edges into CSR slots, precompute normalization coef
__global__ void k_fill(const int* __restrict__ src,
                       const int* __restrict__ dst, int E) {
    int e = blockIdx.x * blockDim.x + threadIdx.x;
    if (e >= E) return;
    int d = dst[e];
    int s = src[e];
    int pos = g_off[d] + atomicAdd(&g_cnt[d], 1);
    g_csr_src[pos] = s;
    g_csr_coef[pos] = g_dinv[s] * g_dinv[d];
}

// ---------------------------------------------------------------------------
// GEMM: Y[N,128] = X[N,128] @ W[128,128]
// 64-row tile per block, 256 threads, each thread: 8 rows x 4 cols.
__global__ void __launch_bounds__(256, 2)
k_gemm(const float* __restrict__ X0, const float* __restrict__ W, int N, int use_x0) {
    __shared__ float Xs[64 * D];
    const float* __restrict__ X = use_x0 ? X0 : g_h1;
    int tid = threadIdx.x;
    int row0 = blockIdx.x * 64;

    #pragma unroll
    for (int i = tid; i < 64 * 32; i += 256) {
        int r = i >> 5, c = i & 31;
        int gr = row0 + r;
        float4 v = make_float4(0.f, 0.f, 0.f, 0.f);
        if (gr < N) v = __ldg((const float4*)(X + (size_t)gr * D) + c);
        ((float4*)Xs)[i] = v;
    }
    __syncthreads();

    int tx = tid & 31, ty = tid >> 5;
    float acc[8][4];
    #pragma unroll
    for (int j = 0; j < 8; j++)
        acc[j][0] = acc[j][1] = acc[j][2] = acc[j][3] = 0.f;

    const float4* Wv = (const float4*)W;
    #pragma unroll 4
    for (int k = 0; k < D; k++) {
        float4 w = __ldg(Wv + k * 32 + tx);
        #pragma unroll
        for (int j = 0; j < 8; j++) {
            float a = Xs[(ty * 8 + j) * D + k];
            acc[j][0] = fmaf(a, w.x, acc[j][0]);
            acc[j][1] = fmaf(a, w.y, acc[j][1]);
            acc[j][2] = fmaf(a, w.z, acc[j][2]);
            acc[j][3] = fmaf(a, w.w, acc[j][3]);
        }
    }
    #pragma unroll
    for (int j = 0; j < 8; j++) {
        int gr = row0 + ty * 8 + j;
        if (gr < N)
            ((float4*)(g_h2 + (size_t)gr * D))[tx] =
                make_float4(acc[j][0], acc[j][1], acc[j][2], acc[j][3]);
    }
}

// ---------------------------------------------------------------------------
// Aggregate: h1[n] = relu( sum_{e: dst=n} coef_e * h2[src_e] + dinv[n]^2*h2[n] + b )
// One warp per node, lane handles 4 columns (float4). 4-edge unroll for MLP.
__global__ void __launch_bounds__(256)
k_agg(const float* __restrict__ bias, int N) {
    int warp = (blockIdx.x * blockDim.x + threadIdx.x) >> 5;
    int lane = threadIdx.x & 31;
    if (warp >= N) return;
    int n = warp;

    const float* __restrict__ T = g_h2;
    float di = g_dinv[n];
    float cs = di * di;
    float4 t = __ldg((const float4*)(T + (size_t)n * D) + lane);
    float4 acc = make_float4(cs * t.x, cs * t.y, cs * t.z, cs * t.w);

    int j = g_off[n], end = g_off[n + 1];
    for (; j + 4 <= end; j += 4) {
        int s0 = g_csr_src[j + 0], s1 = g_csr_src[j + 1];
        int s2 = g_csr_src[j + 2], s3 = g_csr_src[j + 3];
        float c0 = g_csr_coef[j + 0], c1 = g_csr_coef[j + 1];
        float c2 = g_csr_coef[j + 2], c3 = g_csr_coef[j + 3];
        float4 v0 = __ldg((const float4*)(T + (size_t)s0 * D) + lane);
        float4 v1 = __ldg((const float4*)(T + (size_t)s1 * D) + lane);
        float4 v2 = __ldg((const float4*)(T + (size_t)s2 * D) + lane);
        float4 v3 = __ldg((const float4*)(T + (size_t)s3 * D) + lane);
        acc.x = fmaf(c0, v0.x, acc.x); acc.y = fmaf(c0, v0.y, acc.y);
        acc.z = fmaf(c0, v0.z, acc.z); acc.w = fmaf(c0, v0.w, acc.w);
        acc.x = fmaf(c1, v1.x, acc.x); acc.y = fmaf(c1, v1.y, acc.y);
        acc.z = fmaf(c1, v1.z, acc.z); acc.w = fmaf(c1, v1.w, acc.w);
        acc.x = fmaf(c2, v2.x, acc.x); acc.y = fmaf(c2, v2.y, acc.y);
        acc.z = fmaf(c2, v2.z, acc.z); acc.w = fmaf(c2, v2.w, acc.w);
        acc.x = fmaf(c3, v3.x, acc.x); acc.y = fmaf(c3, v3.y, acc.y);
        acc.z = fmaf(c3, v3.z, acc.z); acc.w = fmaf(c3, v3.w, acc.w);
    }
    for (; j < end; j++) {
        int s = g_csr_src[j];
        float c = g_csr_coef[j];
        float4 v = __ldg((const float4*)(T + (size_t)s * D) + lane);
        acc.x = fmaf(c, v.x, acc.x); acc.y = fmaf(c, v.y, acc.y);
        acc.z = fmaf(c, v.z, acc.z); acc.w = fmaf(c, v.w, acc.w);
    }

    float4 b = __ldg((const float4*)bias + lane);
    acc.x = fmaxf(acc.x + b.x, 0.f);
    acc.y = fmaxf(acc.y + b.y, 0.f);
    acc.z = fmaxf(acc.z + b.z, 0.f);
    acc.w = fmaxf(acc.w + b.w, 0.f);
    ((float4*)(g_h1 + (size_t)n * D))[lane] = acc;
}

// ---------------------------------------------------------------------------
// Pool: atomic sums into out (pre-zeroed), counts into g_gcnt
__global__ void __launch_bounds__(256)
k_pool(const int* __restrict__ batch, float* __restrict__ out, int N) {
    int warp = (blockIdx.x * blockDim.x + threadIdx.x) >> 5;
    int lane = threadIdx.x & 31;
    if (warp >= N) return;
    int g = batch[warp];
    float4 v = ((const float4*)(g_h1 + (size_t)warp * D))[lane];
    float* o = out + (size_t)g * D + lane * 4;
    atomicAdd(o + 0, v.x);
    atomicAdd(o + 1, v.y);
    atomicAdd(o + 2, v.z);
    atomicAdd(o + 3, v.w);
    if (lane == 0) atomicAdd(&g_gcnt[g], 1.f);
}

__global__ void k_div(float* __restrict__ out) {
    int i = blockIdx.x * blockDim.x + threadIdx.x;
    if (i < NGRAPH * D) out[i] = out[i] / fmaxf(g_gcnt[i >> 7], 1.f);
}

// ---------------------------------------------------------------------------
extern "C" void kernel_launch(void* const* d_in, const int* in_sizes, int n_in,
                              void* d_out, int out_size) {
    const float* x  = (const float*)d_in[0];
    // d_in[1] = edge_attr (unused by GCNConv)
    const float* W1 = (const float*)d_in[2];
    const float* b1 = (const float*)d_in[3];
    const float* W2 = (const float*)d_in[4];
    const float* b2 = (const float*)d_in[5];
    const float* W3 = (const float*)d_in[6];
    const float* b3 = (const float*)d_in[7];
    const int* ei    = (const int*)d_in[8];
    const int* batch = (const int*)d_in[9];
    float* out = (float*)d_out;

    int N = in_sizes[0] / D;
    int E = in_sizes[8] / 2;
    const int* src = ei;
    const int* dst = ei + E;

    int span = N > NGRAPH * D ? N : NGRAPH * D;   // cover both N and out
    int initb = (span + 255) / 256;
    int nb = (N + 255) / 256;
    int eb = (E + 255) / 256;
    int gb = (N + 63) / 64;
    int ab = ((N * 32) + 255) / 256;

    // graph-structure preprocessing (per launch; deterministic)
    k_init<<<initb, 256>>>(out, N);
    k_count<<<eb, 256>>>(dst, E);
    k_dinv<<<nb, 256>>>(N);
    k_scan<<<1, 1024>>>(N);
    k_fill<<<eb, 256>>>(src, dst, E);

    // layer 1: x -> h1
    k_gemm<<<gb, 256>>>(x, W1, N, 1);
    k_agg<<<ab, 256>>>(b1, N);
    // layer 2: h1 -> h1
    k_gemm<<<gb, 256>>>(x, W2, N, 0);
    k_agg<<<ab, 256>>>(b2, N);
    // layer 3: h1 -> h1
    k_gemm<<<gb, 256>>>(x, W3, N, 0);
    k_agg<<<ab, 256>>>(b3, N);

    // global mean pool
    k_pool<<<ab, 256>>>(batch, out, N);
    k_div<<<(NGRAPH * D + 255) / 256, 256>>>(out);
}

// round 3
// speedup vs baseline: 1.2002x; 1.2002x over previous
#include <cuda_runtime.h>
#include <cuda_bf16.h>

// ---------------------------------------------------------------------------
// GraphBackboneGCN: 3x (GCNConv + ReLU) + global mean pool.
//   N = 50000 nodes, E = 800000 edges, D = H = 128, 512 graphs.
//   edge_index / batch arrive as int32.
// R3: replaced the 109us single-block scan with a 3-phase multi-block scan
//     (fused dinv + cnt-zeroing into phase 1).
// ---------------------------------------------------------------------------

#define NMAX 50176
#define EMAX 1048576
#define D 128
#define NGRAPH 512

#define SCAN_T 1024
#define SCAN_V 4
#define SCAN_ELEMS (SCAN_T * SCAN_V)   // 4096 per block

__device__ __align__(128) float g_h1[(size_t)NMAX * D];   // layer output
__device__ __align__(128) float g_h2[(size_t)NMAX * D];   // gemm tmp
__device__ float g_dinv[NMAX];
__device__ int   g_cnt[NMAX];          // per-dst edge count, then fill cursor
__device__ int   g_off[NMAX + 1];      // CSR row offsets
__device__ int   g_bsum[64];           // per-block scan sums
__device__ int   g_csr_src[EMAX];
__device__ __align__(128) float g_csr_coef[EMAX];
__device__ float g_gcnt[NGRAPH];

// ---------------------------------------------------------------------------
// init: zero counters, graph counts, and the output buffer
__global__ void k_init(float* __restrict__ out, int N) {
    int i = blockIdx.x * blockDim.x + threadIdx.x;
    if (i < N) g_cnt[i] = 0;
    if (i < NGRAPH) g_gcnt[i] = 0.f;
    if (i < NGRAPH * D) out[i] = 0.f;
}

// count in-degree per dst
__global__ void k_count(const int* __restrict__ dst, int E) {
    int e = blockIdx.x * blockDim.x + threadIdx.x;
    if (e < E) atomicAdd(&g_cnt[dst[e]], 1);
}

// ---------------------------------------------------------------------------
// scan phase 1: per-block exclusive scan of g_cnt into g_off, block sums out.
// Fused: dinv = (deg+1)^-0.5 and cnt zeroing (cursor reuse in k_fill).
__global__ void __launch_bounds__(SCAN_T)
k_scan1(int N) {
    __shared__ int s[SCAN_T];
    int tid = threadIdx.x;
    int base = blockIdx.x * SCAN_ELEMS + tid * SCAN_V;
    int v[SCAN_V];
    int sum = 0;
    #pragma unroll
    for (int k = 0; k < SCAN_V; k++) {
        int i = base + k;
        v[k] = (i < N) ? g_cnt[i] : 0;
        if (i < N) {
            g_dinv[i] = rsqrtf((float)(v[k] + 1));
            g_cnt[i] = 0;
        }
        sum += v[k];
    }
    s[tid] = sum;
    __syncthreads();
    for (int d2 = 1; d2 < SCAN_T; d2 <<= 1) {
        int t = (tid >= d2) ? s[tid - d2] : 0;
        __syncthreads();
        s[tid] += t;
        __syncthreads();
    }
    int excl = s[tid] - sum;   // exclusive prefix within block
    #pragma unroll
    for (int k = 0; k < SCAN_V; k++) {
        int i = base + k;
        if (i < N) g_off[i] = excl;
        excl += v[k];
    }
    if (tid == SCAN_T - 1) g_bsum[blockIdx.x] = s[tid];
}

// scan phase 2: one warp scans block sums (inclusive), writes g_off[N]=E total
__global__ void k_scan2(int nb, int N) {
    int tid = threadIdx.x;
    int v = (tid < nb) ? g_bsum[tid] : 0;
    #pragma unroll
    for (int d2 = 1; d2 < 32; d2 <<= 1) {
        int t = __shfl_up_sync(0xffffffffu, v, d2);
        if (tid >= d2) v += t;
    }
    if (tid < nb) g_bsum[tid] = v;          // inclusive
    if (tid == nb - 1) g_off[N] = v;        // total edge count
}

// scan phase 3: add predecessor-block prefix
__global__ void __launch_bounds__(SCAN_T)
k_scan3(int N) {
    if (blockIdx.x == 0) return;
    int add = g_bsum[blockIdx.x - 1];
    int base = blockIdx.x * SCAN_ELEMS + threadIdx.x;
    #pragma unroll
    for (int k = 0; k < SCAN_V; k++) {
        int i = base + k * SCAN_T;
        if (i < N) g_off[i] += add;
    }
}

// scatter edges into CSR slots, precompute normalization coef
__global__ void k_fill(const int* __restrict__ src,
                       const int* __restrict__ dst, int E) {
    int e = blockIdx.x * blockDim.x + threadIdx.x;
    if (e >= E) return;
    int d = dst[e];
    int s = src[e];
    int pos = g_off[d] + atomicAdd(&g_cnt[d], 1);
    g_csr_src[pos] = s;
    g_csr_coef[pos] = g_dinv[s] * g_dinv[d];
}

// ---------------------------------------------------------------------------
// GEMM: Y[N,128] = X[N,128] @ W[128,128]
// 64-row tile per block, 256 threads, each thread: 8 rows x 4 cols.
__global__ void __launch_bounds__(256, 2)
k_gemm(const float* __restrict__ X0, const float* __restrict__ W, int N, int use_x0) {
    __shared__ float Xs[64 * D];
    const float* __restrict__ X = use_x0 ? X0 : g_h1;
    int tid = threadIdx.x;
    int row0 = blockIdx.x * 64;

    #pragma unroll
    for (int i = tid; i < 64 * 32; i += 256) {
        int r = i >> 5, c = i & 31;
        int gr = row0 + r;
        float4 v = make_float4(0.f, 0.f, 0.f, 0.f);
        if (gr < N) v = __ldg((const float4*)(X + (size_t)gr * D) + c);
        ((float4*)Xs)[i] = v;
    }
    __syncthreads();

    int tx = tid & 31, ty = tid >> 5;
    float acc[8][4];
    #pragma unroll
    for (int j = 0; j < 8; j++)
        acc[j][0] = acc[j][1] = acc[j][2] = acc[j][3] = 0.f;

    const float4* Wv = (const float4*)W;
    #pragma unroll 4
    for (int k = 0; k < D; k++) {
        float4 w = __ldg(Wv + k * 32 + tx);
        #pragma unroll
        for (int j = 0; j < 8; j++) {
            float a = Xs[(ty * 8 + j) * D + k];
            acc[j][0] = fmaf(a, w.x, acc[j][0]);
            acc[j][1] = fmaf(a, w.y, acc[j][1]);
            acc[j][2] = fmaf(a, w.z, acc[j][2]);
            acc[j][3] = fmaf(a, w.w, acc[j][3]);
        }
    }
    #pragma unroll
    for (int j = 0; j < 8; j++) {
        int gr = row0 + ty * 8 + j;
        if (gr < N)
            ((float4*)(g_h2 + (size_t)gr * D))[tx] =
                make_float4(acc[j][0], acc[j][1], acc[j][2], acc[j][3]);
    }
}

// ---------------------------------------------------------------------------
// Aggregate: h1[n] = relu( sum_{e: dst=n} coef_e * h2[src_e] + dinv[n]^2*h2[n] + b )
// One warp per node, lane handles 4 columns (float4). 4-edge unroll for MLP.
__global__ void __launch_bounds__(256)
k_agg(const float* __restrict__ bias, int N) {
    int warp = (blockIdx.x * blockDim.x + threadIdx.x) >> 5;
    int lane = threadIdx.x & 31;
    if (warp >= N) return;
    int n = warp;

    const float* __restrict__ T = g_h2;
    float di = g_dinv[n];
    float cs = di * di;
    float4 t = __ldg((const float4*)(T + (size_t)n * D) + lane);
    float4 acc = make_float4(cs * t.x, cs * t.y, cs * t.z, cs * t.w);

    int j = g_off[n], end = g_off[n + 1];
    for (; j + 4 <= end; j += 4) {
        int s0 = g_csr_src[j + 0], s1 = g_csr_src[j + 1];
        int s2 = g_csr_src[j + 2], s3 = g_csr_src[j + 3];
        float c0 = g_csr_coef[j + 0], c1 = g_csr_coef[j + 1];
        float c2 = g_csr_coef[j + 2], c3 = g_csr_coef[j + 3];
        float4 v0 = __ldg((const float4*)(T + (size_t)s0 * D) + lane);
        float4 v1 = __ldg((const float4*)(T + (size_t)s1 * D) + lane);
        float4 v2 = __ldg((const float4*)(T + (size_t)s2 * D) + lane);
        float4 v3 = __ldg((const float4*)(T + (size_t)s3 * D) + lane);
        acc.x = fmaf(c0, v0.x, acc.x); acc.y = fmaf(c0, v0.y, acc.y);
        acc.z = fmaf(c0, v0.z, acc.z); acc.w = fmaf(c0, v0.w, acc.w);
        acc.x = fmaf(c1, v1.x, acc.x); acc.y = fmaf(c1, v1.y, acc.y);
        acc.z = fmaf(c1, v1.z, acc.z); acc.w = fmaf(c1, v1.w, acc.w);
        acc.x = fmaf(c2, v2.x, acc.x); acc.y = fmaf(c2, v2.y, acc.y);
        acc.z = fmaf(c2, v2.z, acc.z); acc.w = fmaf(c2, v2.w, acc.w);
        acc.x = fmaf(c3, v3.x, acc.x); acc.y = fmaf(c3, v3.y, acc.y);
        acc.z = fmaf(c3, v3.z, acc.z); acc.w = fmaf(c3, v3.w, acc.w);
    }
    for (; j < end; j++) {
        int s = g_csr_src[j];
        float c = g_csr_coef[j];
        float4 v = __ldg((const float4*)(T + (size_t)s * D) + lane);
        acc.x = fmaf(c, v.x, acc.x); acc.y = fmaf(c, v.y, acc.y);
        acc.z = fmaf(c, v.z, acc.z); acc.w = fmaf(c, v.w, acc.w);
    }

    float4 b = __ldg((const float4*)bias + lane);
    acc.x = fmaxf(acc.x + b.x, 0.f);
    acc.y = fmaxf(acc.y + b.y, 0.f);
    acc.z = fmaxf(acc.z + b.z, 0.f);
    acc.w = fmaxf(acc.w + b.w, 0.f);
    ((float4*)(g_h1 + (size_t)n * D))[lane] = acc;
}

// ---------------------------------------------------------------------------
// Pool: atomic sums into out (pre-zeroed), counts into g_gcnt
__global__ void __launch_bounds__(256)
k_pool(const int* __restrict__ batch, float* __restrict__ out, int N) {
    int warp = (blockIdx.x * blockDim.x + threadIdx.x) >> 5;
    int lane = threadIdx.x & 31;
    if (warp >= N) return;
    int g = batch[warp];
    float4 v = ((const float4*)(g_h1 + (size_t)warp * D))[lane];
    float* o = out + (size_t)g * D + lane * 4;
    atomicAdd(o + 0, v.x);
    atomicAdd(o + 1, v.y);
    atomicAdd(o + 2, v.z);
    atomicAdd(o + 3, v.w);
    if (lane == 0) atomicAdd(&g_gcnt[g], 1.f);
}

__global__ void k_div(float* __restrict__ out) {
    int i = blockIdx.x * blockDim.x + threadIdx.x;
    if (i < NGRAPH * D) out[i] = out[i] / fmaxf(g_gcnt[i >> 7], 1.f);
}

// ---------------------------------------------------------------------------
extern "C" void kernel_launch(void* const* d_in, const int* in_sizes, int n_in,
                              void* d_out, int out_size) {
    const float* x  = (const float*)d_in[0];
    // d_in[1] = edge_attr (unused by GCNConv)
    const float* W1 = (const float*)d_in[2];
    const float* b1 = (const float*)d_in[3];
    const float* W2 = (const float*)d_in[4];
    const float* b2 = (const float*)d_in[5];
    const float* W3 = (const float*)d_in[6];
    const float* b3 = (const float*)d_in[7];
    const int* ei    = (const int*)d_in[8];
    const int* batch = (const int*)d_in[9];
    float* out = (float*)d_out;

    int N = in_sizes[0] / D;
    int E = in_sizes[8] / 2;
    const int* src = ei;
    const int* dst = ei + E;

    int span = N > NGRAPH * D ? N : NGRAPH * D;   // cover both N and out
    int initb = (span + 255) / 256;
    int eb = (E + 255) / 256;
    int gb = (N + 63) / 64;
    int ab = ((N * 32) + 255) / 256;
    int sb = (N + SCAN_ELEMS - 1) / SCAN_ELEMS;   // scan blocks (13)

    // graph-structure preprocessing (per launch; deterministic)
    k_init<<<initb, 256>>>(out, N);
    k_count<<<eb, 256>>>(dst, E);
    k_scan1<<<sb, SCAN_T>>>(N);
    k_scan2<<<1, 32>>>(sb, N);
    k_scan3<<<sb, SCAN_T>>>(N);
    k_fill<<<eb, 256>>>(src, dst, E);

    // layer 1: x -> h1
    k_gemm<<<gb, 256>>>(x, W1, N, 1);
    k_agg<<<ab, 256>>>(b1, N);
    // layer 2: h1 -> h1
    k_gemm<<<gb, 256>>>(x, W2, N, 0);
    k_agg<<<ab, 256>>>(b2, N);
    // layer 3: h1 -> h1
    k_gemm<<<gb, 256>>>(x, W3, N, 0);
    k_agg<<<ab, 256>>>(b3, N);

    // global mean pool
    k_pool<<<ab, 256>>>(batch, out, N);
    k_div<<<(NGRAPH * D + 255) / 256, 256>>>(out);
}

// round 4
// speedup vs baseline: 1.5471x; 1.2891x over previous
#include <cuda_runtime.h>
#include <cuda_fp16.h>

// ---------------------------------------------------------------------------
// GraphBackboneGCN: 3x (GCNConv + ReLU) + global mean pool.
// R4: fp16 gather source (h2), k-vectorized GEMM inner loop, pool fused into
//     layer-3 aggregation, packed CSR entries.
// ---------------------------------------------------------------------------

#define NMAX 50176
#define EMAX 1048576
#define D 128
#define NGRAPH 512

#define SCAN_T 1024
#define SCAN_V 4
#define SCAN_ELEMS (SCAN_T * SCAN_V)   // 4096 per block

__device__ __align__(128) float  g_h1[(size_t)NMAX * D];   // layer output (fp32)
__device__ __align__(128) __half g_h2[(size_t)NMAX * D];   // gemm out / gather src (fp16)
__device__ float g_dinv[NMAX];
__device__ int   g_cnt[NMAX];          // per-dst edge count, then fill cursor
__device__ int   g_off[NMAX + 1];      // CSR row offsets
__device__ int   g_bsum[64];           // per-block scan sums
__device__ __align__(128) int2 g_csr[EMAX];   // .x = src, .y = coef bits
__device__ float g_gcnt[NGRAPH];

// ---------------------------------------------------------------------------
__global__ void k_init(float* __restrict__ out, int N) {
    int i = blockIdx.x * blockDim.x + threadIdx.x;
    if (i < N) g_cnt[i] = 0;
    if (i < NGRAPH) g_gcnt[i] = 0.f;
    if (i < NGRAPH * D) out[i] = 0.f;
}

__global__ void k_count(const int* __restrict__ dst, int E) {
    int e = blockIdx.x * blockDim.x + threadIdx.x;
    if (e < E) atomicAdd(&g_cnt[dst[e]], 1);
}

// ---------------------------------------------------------------------------
// scan phase 1: per-block exclusive scan of g_cnt into g_off, block sums out.
// Fused: dinv, cnt zeroing, per-graph node counts.
__global__ void __launch_bounds__(SCAN_T)
k_scan1(const int* __restrict__ batch, int N) {
    __shared__ int s[SCAN_T];
    int tid = threadIdx.x;
    int base = blockIdx.x * SCAN_ELEMS + tid * SCAN_V;
    int v[SCAN_V];
    int sum = 0;
    #pragma unroll
    for (int k = 0; k < SCAN_V; k++) {
        int i = base + k;
        v[k] = (i < N) ? g_cnt[i] : 0;
        if (i < N) {
            g_dinv[i] = rsqrtf((float)(v[k] + 1));
            g_cnt[i] = 0;
            atomicAdd(&g_gcnt[batch[i]], 1.f);
        }
        sum += v[k];
    }
    s[tid] = sum;
    __syncthreads();
    for (int d2 = 1; d2 < SCAN_T; d2 <<= 1) {
        int t = (tid >= d2) ? s[tid - d2] : 0;
        __syncthreads();
        s[tid] += t;
        __syncthreads();
    }
    int excl = s[tid] - sum;
    #pragma unroll
    for (int k = 0; k < SCAN_V; k++) {
        int i = base + k;
        if (i < N) g_off[i] = excl;
        excl += v[k];
    }
    if (tid == SCAN_T - 1) g_bsum[blockIdx.x] = s[tid];
}

__global__ void k_scan2(int nb, int N) {
    int tid = threadIdx.x;
    int v = (tid < nb) ? g_bsum[tid] : 0;
    #pragma unroll
    for (int d2 = 1; d2 < 32; d2 <<= 1) {
        int t = __shfl_up_sync(0xffffffffu, v, d2);
        if (tid >= d2) v += t;
    }
    if (tid < nb) g_bsum[tid] = v;
    if (tid == nb - 1) g_off[N] = v;
}

__global__ void __launch_bounds__(SCAN_T)
k_scan3(int N) {
    if (blockIdx.x == 0) return;
    int add = g_bsum[blockIdx.x - 1];
    int base = blockIdx.x * SCAN_ELEMS + threadIdx.x;
    #pragma unroll
    for (int k = 0; k < SCAN_V; k++) {
        int i = base + k * SCAN_T;
        if (i < N) g_off[i] += add;
    }
}

// scatter edges into CSR slots (packed 8B entries)
__global__ void k_fill(const int* __restrict__ src,
                       const int* __restrict__ dst, int E) {
    int e = blockIdx.x * blockDim.x + threadIdx.x;
    if (e >= E) return;
    int d = dst[e];
    int s = src[e];
    int pos = g_off[d] + atomicAdd(&g_cnt[d], 1);
    float coef = g_dinv[s] * g_dinv[d];
    g_csr[pos] = make_int2(s, __float_as_int(coef));
}

// ---------------------------------------------------------------------------
// GEMM: h2[N,128] (fp16) = X[N,128] @ W[128,128]   (fp32 math)
// 64-row tile, 256 threads, 8 rows x 4 cols per thread, k-vectorized by 4.
__global__ void __launch_bounds__(256, 2)
k_gemm(const float* __restrict__ X0, const float* __restrict__ W, int N, int use_x0) {
    __shared__ float Xs[64 * D];
    const float* __restrict__ X = use_x0 ? X0 : g_h1;
    int tid = threadIdx.x;
    int row0 = blockIdx.x * 64;

    #pragma unroll
    for (int i = tid; i < 64 * 32; i += 256) {
        int r = i >> 5, c = i & 31;
        int gr = row0 + r;
        float4 v = make_float4(0.f, 0.f, 0.f, 0.f);
        if (gr < N) v = __ldg((const float4*)(X + (size_t)gr * D) + c);
        ((float4*)Xs)[i] = v;
    }
    __syncthreads();

    int tx = tid & 31, ty = tid >> 5;
    float acc[8][4];
    #pragma unroll
    for (int j = 0; j < 8; j++)
        acc[j][0] = acc[j][1] = acc[j][2] = acc[j][3] = 0.f;

    const float4* Wv = (const float4*)W;
    #pragma unroll 2
    for (int kk = 0; kk < D; kk += 4) {
        float4 w0 = __ldg(Wv + (kk + 0) * 32 + tx);
        float4 w1 = __ldg(Wv + (kk + 1) * 32 + tx);
        float4 w2 = __ldg(Wv + (kk + 2) * 32 + tx);
        float4 w3 = __ldg(Wv + (kk + 3) * 32 + tx);
        #pragma unroll
        for (int j = 0; j < 8; j++) {
            float4 a = *(const float4*)&Xs[(ty * 8 + j) * D + kk];
            acc[j][0] = fmaf(a.x, w0.x, acc[j][0]);
            acc[j][1] = fmaf(a.x, w0.y, acc[j][1]);
            acc[j][2] = fmaf(a.x, w0.z, acc[j][2]);
            acc[j][3] = fmaf(a.x, w0.w, acc[j][3]);
            acc[j][0] = fmaf(a.y, w1.x, acc[j][0]);
            acc[j][1] = fmaf(a.y, w1.y, acc[j][1]);
            acc[j][2] = fmaf(a.y, w1.z, acc[j][2]);
            acc[j][3] = fmaf(a.y, w1.w, acc[j][3]);
            acc[j][0] = fmaf(a.z, w2.x, acc[j][0]);
            acc[j][1] = fmaf(a.z, w2.y, acc[j][1]);
            acc[j][2] = fmaf(a.z, w2.z, acc[j][2]);
            acc[j][3] = fmaf(a.z, w2.w, acc[j][3]);
            acc[j][0] = fmaf(a.w, w3.x, acc[j][0]);
            acc[j][1] = fmaf(a.w, w3.y, acc[j][1]);
            acc[j][2] = fmaf(a.w, w3.z, acc[j][2]);
            acc[j][3] = fmaf(a.w, w3.w, acc[j][3]);
        }
    }
    // write as fp16 (half2 pairs), lane tx covers cols tx*4 .. tx*4+3
    #pragma unroll
    for (int j = 0; j < 8; j++) {
        int gr = row0 + ty * 8 + j;
        if (gr < N) {
            __half2 lo = __floats2half2_rn(acc[j][0], acc[j][1]);
            __half2 hi = __floats2half2_rn(acc[j][2], acc[j][3]);
            *(uint2*)(g_h2 + (size_t)gr * D + tx * 4) =
                make_uint2(*(unsigned*)&lo, *(unsigned*)&hi);
        }
    }
}

// ---------------------------------------------------------------------------
// gather one fp16 row chunk (4 halves) and accumulate
__device__ __forceinline__ void agg_edge(float4& acc, const __half* T,
                                         int s, float c, int lane) {
    uint2 p = __ldg((const uint2*)(T + (size_t)s * D) + lane);
    float2 v0 = __half22float2(*(const __half2*)&p.x);
    float2 v1 = __half22float2(*(const __half2*)&p.y);
    acc.x = fmaf(c, v0.x, acc.x);
    acc.y = fmaf(c, v0.y, acc.y);
    acc.z = fmaf(c, v1.x, acc.z);
    acc.w = fmaf(c, v1.y, acc.w);
}

__device__ __forceinline__ float4 agg_node(const float* __restrict__ bias,
                                           int n, int lane) {
    const __half* T = g_h2;
    float di = g_dinv[n];
    float cs = di * di;
    float4 acc = make_float4(0.f, 0.f, 0.f, 0.f);
    agg_edge(acc, T, n, cs, lane);   // self-loop

    int j = g_off[n], end = g_off[n + 1];
    for (; j + 4 <= end; j += 4) {
        int2 e0 = g_csr[j + 0];
        int2 e1 = g_csr[j + 1];
        int2 e2 = g_csr[j + 2];
        int2 e3 = g_csr[j + 3];
        agg_edge(acc, T, e0.x, __int_as_float(e0.y), lane);
        agg_edge(acc, T, e1.x, __int_as_float(e1.y), lane);
        agg_edge(acc, T, e2.x, __int_as_float(e2.y), lane);
        agg_edge(acc, T, e3.x, __int_as_float(e3.y), lane);
    }
    for (; j < end; j++) {
        int2 e = g_csr[j];
        agg_edge(acc, T, e.x, __int_as_float(e.y), lane);
    }

    float4 b = __ldg((const float4*)bias + lane);
    acc.x = fmaxf(acc.x + b.x, 0.f);
    acc.y = fmaxf(acc.y + b.y, 0.f);
    acc.z = fmaxf(acc.z + b.z, 0.f);
    acc.w = fmaxf(acc.w + b.w, 0.f);
    return acc;
}

// layers 1-2: write h1 (fp32) for next GEMM
__global__ void __launch_bounds__(256)
k_agg(const float* __restrict__ bias, int N) {
    int warp = (blockIdx.x * blockDim.x + threadIdx.x) >> 5;
    int lane = threadIdx.x & 31;
    if (warp >= N) return;
    float4 acc = agg_node(bias, warp, lane);
    ((float4*)(g_h1 + (size_t)warp * D))[lane] = acc;
}

// layer 3: fused global mean-pool (sum via atomics; div later)
__global__ void __launch_bounds__(256)
k_agg_pool(const float* __restrict__ bias, const int* __restrict__ batch,
           float* __restrict__ out, int N) {
    int warp = (blockIdx.x * blockDim.x + threadIdx.x) >> 5;
    int lane = threadIdx.x & 31;
    if (warp >= N) return;
    float4 acc = agg_node(bias, warp, lane);
    int g = batch[warp];
    float* o = out + (size_t)g * D + lane * 4;
    atomicAdd(o + 0, acc.x);
    atomicAdd(o + 1, acc.y);
    atomicAdd(o + 2, acc.z);
    atomicAdd(o + 3, acc.w);
}

__global__ void k_div(float* __restrict__ out) {
    int i = blockIdx.x * blockDim.x + threadIdx.x;
    if (i < NGRAPH * D) out[i] = out[i] / fmaxf(g_gcnt[i >> 7], 1.f);
}

// ---------------------------------------------------------------------------
extern "C" void kernel_launch(void* const* d_in, const int* in_sizes, int n_in,
                              void* d_out, int out_size) {
    const float* x  = (const float*)d_in[0];
    // d_in[1] = edge_attr (unused by GCNConv)
    const float* W1 = (const float*)d_in[2];
    const float* b1 = (const float*)d_in[3];
    const float* W2 = (const float*)d_in[4];
    const float* b2 = (const float*)d_in[5];
    const float* W3 = (const float*)d_in[6];
    const float* b3 = (const float*)d_in[7];
    const int* ei    = (const int*)d_in[8];
    const int* batch = (const int*)d_in[9];
    float* out = (float*)d_out;

    int N = in_sizes[0] / D;
    int E = in_sizes[8] / 2;
    const int* src = ei;
    const int* dst = ei + E;

    int span = N > NGRAPH * D ? N : NGRAPH * D;
    int initb = (span + 255) / 256;
    int eb = (E + 255) / 256;
    int gb = (N + 63) / 64;
    int ab = ((N * 32) + 255) / 256;
    int sb = (N + SCAN_ELEMS - 1) / SCAN_ELEMS;

    // graph-structure preprocessing
    k_init<<<initb, 256>>>(out, N);
    k_count<<<eb, 256>>>(dst, E);
    k_scan1<<<sb, SCAN_T>>>(batch, N);
    k_scan2<<<1, 32>>>(sb, N);
    k_scan3<<<sb, SCAN_T>>>(N);
    k_fill<<<eb, 256>>>(src, dst, E);

    // layer 1: x -> h1
    k_gemm<<<gb, 256>>>(x, W1, N, 1);
    k_agg<<<ab, 256>>>(b1, N);
    // layer 2: h1 -> h1
    k_gemm<<<gb, 256>>>(x, W2, N, 0);
    k_agg<<<ab, 256>>>(b2, N);
    // layer 3: h1 -> out (fused pool)
    k_gemm<<<gb, 256>>>(x, W3, N, 0);
    k_agg_pool<<<ab, 256>>>(b3, batch, out, N);

    k_div<<<(NGRAPH * D + 255) / 256, 256>>>(out);
}

// round 5
// speedup vs baseline: 2.2251x; 1.4382x over previous
#include <cuda_runtime.h>
#include <cuda_fp16.h>
#include <cstdint>

// ---------------------------------------------------------------------------
// GraphBackboneGCN: 3x (GCNConv + ReLU) + global mean pool.
// R5: tensor-core GEMM (mma.m16n8k16 f16->f32), W pre-packed into fragment
//     order, h1 stored fp16, fp16 gather (h2), fused layer-3 pool.
// ---------------------------------------------------------------------------

#define NMAX 50176
#define EMAX 1048576
#define D 128
#define NGRAPH 512

#define SCAN_T 1024
#define SCAN_V 4
#define SCAN_ELEMS (SCAN_T * SCAN_V)

__device__ __align__(128) __half g_h1[(size_t)NMAX * D];   // agg out (fp16)
__device__ __align__(128) __half g_h2[(size_t)NMAX * D];   // gemm out / gather src
__device__ float g_dinv[NMAX];
__device__ int   g_cnt[NMAX];
__device__ int   g_off[NMAX + 1];
__device__ int   g_bsum[64];
__device__ __align__(128) int2 g_csr[EMAX];   // .x = src, .y = coef bits
__device__ float g_gcnt[NGRAPH];
__device__ __align__(128) uint2 g_wb[3][4096]; // W in mma B-fragment order

// ---------------------------------------------------------------------------
__global__ void k_init(float* __restrict__ out, int N) {
    int i = blockIdx.x * blockDim.x + threadIdx.x;
    if (i < N) g_cnt[i] = 0;
    if (i < NGRAPH) g_gcnt[i] = 0.f;
    if (i < NGRAPH * D) out[i] = 0.f;
}

__global__ void k_count(const int* __restrict__ dst, int E) {
    int e = blockIdx.x * blockDim.x + threadIdx.x;
    if (e < E) atomicAdd(&g_cnt[dst[e]], 1);
}

// pack W[128x128] (row-major, k x n) into m16n8k16 B-fragment order:
// entry[(ks*16+nt)*32+lane] = {pack(W[k0][n],W[k0+1][n]), pack(W[k0+8][n],W[k0+9][n])}
// with tig=lane&3, gid=lane>>2, k0=ks*16+tig*2, n=nt*8+gid.
__global__ void k_wconv(const float* __restrict__ W0, const float* __restrict__ W1,
                        const float* __restrict__ W2) {
    int idx = blockIdx.x * blockDim.x + threadIdx.x;   // 0..4095
    int layer = blockIdx.y;
    const float* W = layer == 0 ? W0 : (layer == 1 ? W1 : W2);
    int lane = idx & 31;
    int nt = (idx >> 5) & 15;
    int ks = idx >> 9;
    int tig = lane & 3, gid = lane >> 2;
    int n = nt * 8 + gid;
    int k0 = ks * 16 + tig * 2;
    __half2 b0 = __floats2half2_rn(W[k0 * D + n],       W[(k0 + 1) * D + n]);
    __half2 b1 = __floats2half2_rn(W[(k0 + 8) * D + n], W[(k0 + 9) * D + n]);
    g_wb[layer][idx] = make_uint2(*(unsigned*)&b0, *(unsigned*)&b1);
}

// ---------------------------------------------------------------------------
// scan phase 1 (fused dinv, cnt zeroing, per-graph counts)
__global__ void __launch_bounds__(SCAN_T)
k_scan1(const int* __restrict__ batch, int N) {
    __shared__ int s[SCAN_T];
    int tid = threadIdx.x;
    int base = blockIdx.x * SCAN_ELEMS + tid * SCAN_V;
    int v[SCAN_V];
    int sum = 0;
    #pragma unroll
    for (int k = 0; k < SCAN_V; k++) {
        int i = base + k;
        v[k] = (i < N) ? g_cnt[i] : 0;
        if (i < N) {
            g_dinv[i] = rsqrtf((float)(v[k] + 1));
            g_cnt[i] = 0;
            atomicAdd(&g_gcnt[batch[i]], 1.f);
        }
        sum += v[k];
    }
    s[tid] = sum;
    __syncthreads();
    for (int d2 = 1; d2 < SCAN_T; d2 <<= 1) {
        int t = (tid >= d2) ? s[tid - d2] : 0;
        __syncthreads();
        s[tid] += t;
        __syncthreads();
    }
    int excl = s[tid] - sum;
    #pragma unroll
    for (int k = 0; k < SCAN_V; k++) {
        int i = base + k;
        if (i < N) g_off[i] = excl;
        excl += v[k];
    }
    if (tid == SCAN_T - 1) g_bsum[blockIdx.x] = s[tid];
}

__global__ void k_scan2(int nb, int N) {
    int tid = threadIdx.x;
    int v = (tid < nb) ? g_bsum[tid] : 0;
    #pragma unroll
    for (int d2 = 1; d2 < 32; d2 <<= 1) {
        int t = __shfl_up_sync(0xffffffffu, v, d2);
        if (tid >= d2) v += t;
    }
    if (tid < nb) g_bsum[tid] = v;
    if (tid == nb - 1) g_off[N] = v;
}

__global__ void __launch_bounds__(SCAN_T)
k_scan3(int N) {
    if (blockIdx.x == 0) return;
    int add = g_bsum[blockIdx.x - 1];
    int base = blockIdx.x * SCAN_ELEMS + threadIdx.x;
    #pragma unroll
    for (int k = 0; k < SCAN_V; k++) {
        int i = base + k * SCAN_T;
        if (i < N) g_off[i] += add;
    }
}

__global__ void k_fill(const int* __restrict__ src,
                       const int* __restrict__ dst, int E) {
    int e = blockIdx.x * blockDim.x + threadIdx.x;
    if (e >= E) return;
    int d = dst[e];
    int s = src[e];
    int pos = g_off[d] + atomicAdd(&g_cnt[d], 1);
    float coef = g_dinv[s] * g_dinv[d];
    g_csr[pos] = make_int2(s, __float_as_int(coef));
}

// ---------------------------------------------------------------------------
// Tensor-core GEMM: h2[N,128](fp16) = X[N,128] @ W[128,128]
// Block: 256 thr / 8 warps, tile 128 rows. Warp: 16 rows x 128 cols.
// A: ldmatrix.x4 from padded fp16 smem; B: LDG.64 from g_wb (L1-hot).
#define XS_STRIDE 136   // halves; 272B row stride -> conflict-free ldmatrix

__global__ void __launch_bounds__(256, 2)
k_gemm(const float* __restrict__ X0, int layer, int N, int use_x0) {
    __shared__ __half Xs[128 * XS_STRIDE];
    int tid = threadIdx.x;
    int lane = tid & 31, wid = tid >> 5;
    int row0 = blockIdx.x * 128;

    // --- load X tile into smem as fp16 ---
    if (use_x0) {
        // fp32 source: 128 rows x 32 float4-chunks
        for (int i = tid; i < 128 * 32; i += 256) {
            int r = i >> 5, c4 = i & 31;       // c4: float4 index (4 cols)
            int gr = row0 + r;
            float4 v = make_float4(0.f, 0.f, 0.f, 0.f);
            if (gr < N) v = __ldg((const float4*)(X0 + (size_t)gr * D) + c4);
            __half2 lo = __floats2half2_rn(v.x, v.y);
            __half2 hi = __floats2half2_rn(v.z, v.w);
            *(uint2*)&Xs[r * XS_STRIDE + c4 * 4] =
                make_uint2(*(unsigned*)&lo, *(unsigned*)&hi);
        }
    } else {
        // fp16 source: 128 rows x 16 uint4-chunks (8 halves each)
        for (int i = tid; i < 128 * 16; i += 256) {
            int r = i >> 4, c8 = i & 15;
            int gr = row0 + r;
            uint4 v = make_uint4(0u, 0u, 0u, 0u);
            if (gr < N) v = __ldg((const uint4*)(g_h1 + (size_t)gr * D) + c8);
            *(uint4*)&Xs[r * XS_STRIDE + c8 * 8] = v;
        }
    }
    __syncthreads();

    // --- mma mainloop ---
    float acc[16][4];
    #pragma unroll
    for (int nt = 0; nt < 16; nt++)
        acc[nt][0] = acc[nt][1] = acc[nt][2] = acc[nt][3] = 0.f;

    // ldmatrix lane -> (row, col8) within 16x16 A tile
    int a_row = (lane & 7) | (((lane >> 3) & 1) << 3);
    int a_col8 = (lane >> 4) * 8;
    const __half* a_base = &Xs[(wid * 16 + a_row) * XS_STRIDE + a_col8];
    const uint2* Wb = g_wb[layer];

    #pragma unroll
    for (int ks = 0; ks < 8; ks++) {
        uint32_t a0, a1, a2, a3;
        uint32_t addr = (uint32_t)__cvta_generic_to_shared(a_base + ks * 16);
        asm volatile(
            "ldmatrix.sync.aligned.m8n8.x4.shared.b16 {%0,%1,%2,%3}, [%4];"
            : "=r"(a0), "=r"(a1), "=r"(a2), "=r"(a3) : "r"(addr));
        #pragma unroll
        for (int nt = 0; nt < 16; nt++) {
            uint2 b = __ldg(Wb + (ks * 16 + nt) * 32 + lane);
            asm volatile(
                "mma.sync.aligned.m16n8k16.row.col.f32.f16.f16.f32 "
                "{%0,%1,%2,%3},{%4,%5,%6,%7},{%8,%9},{%0,%1,%2,%3};"
                : "+f"(acc[nt][0]), "+f"(acc[nt][1]),
                  "+f"(acc[nt][2]), "+f"(acc[nt][3])
                : "r"(a0), "r"(a1), "r"(a2), "r"(a3), "r"(b.x), "r"(b.y));
        }
    }

    // --- store accumulators as fp16 into g_h2 ---
    int tig = lane & 3, gid = lane >> 2;
    int r_lo = row0 + wid * 16 + gid;
    int r_hi = r_lo + 8;
    #pragma unroll
    for (int nt = 0; nt < 16; nt++) {
        int col = nt * 8 + tig * 2;
        if (r_lo < N) {
            __half2 h = __floats2half2_rn(acc[nt][0], acc[nt][1]);
            *(unsigned*)&g_h2[(size_t)r_lo * D + col] = *(unsigned*)&h;
        }
        if (r_hi < N) {
            __half2 h = __floats2half2_rn(acc[nt][2], acc[nt][3]);
            *(unsigned*)&g_h2[(size_t)r_hi * D + col] = *(unsigned*)&h;
        }
    }
}

// ---------------------------------------------------------------------------
__device__ __forceinline__ void agg_edge(float4& acc, const __half* T,
                                         int s, float c, int lane) {
    uint2 p = __ldg((const uint2*)(T + (size_t)s * D) + lane);
    float2 v0 = __half22float2(*(const __half2*)&p.x);
    float2 v1 = __half22float2(*(const __half2*)&p.y);
    acc.x = fmaf(c, v0.x, acc.x);
    acc.y = fmaf(c, v0.y, acc.y);
    acc.z = fmaf(c, v1.x, acc.z);
    acc.w = fmaf(c, v1.y, acc.w);
}

__device__ __forceinline__ float4 agg_node(const float* __restrict__ bias,
                                           int n, int lane) {
    const __half* T = g_h2;
    float di = g_dinv[n];
    float cs = di * di;
    float4 acc = make_float4(0.f, 0.f, 0.f, 0.f);
    agg_edge(acc, T, n, cs, lane);   // self-loop

    int j = g_off[n], end = g_off[n + 1];
    for (; j + 4 <= end; j += 4) {
        int2 e0 = g_csr[j + 0];
        int2 e1 = g_csr[j + 1];
        int2 e2 = g_csr[j + 2];
        int2 e3 = g_csr[j + 3];
        agg_edge(acc, T, e0.x, __int_as_float(e0.y), lane);
        agg_edge(acc, T, e1.x, __int_as_float(e1.y), lane);
        agg_edge(acc, T, e2.x, __int_as_float(e2.y), lane);
        agg_edge(acc, T, e3.x, __int_as_float(e3.y), lane);
    }
    for (; j < end; j++) {
        int2 e = g_csr[j];
        agg_edge(acc, T, e.x, __int_as_float(e.y), lane);
    }

    float4 b = __ldg((const float4*)bias + lane);
    acc.x = fmaxf(acc.x + b.x, 0.f);
    acc.y = fmaxf(acc.y + b.y, 0.f);
    acc.z = fmaxf(acc.z + b.z, 0.f);
    acc.w = fmaxf(acc.w + b.w, 0.f);
    return acc;
}

// layers 1-2: write h1 (fp16) for next GEMM
__global__ void __launch_bounds__(256)
k_agg(const float* __restrict__ bias, int N) {
    int warp = (blockIdx.x * blockDim.x + threadIdx.x) >> 5;
    int lane = threadIdx.x & 31;
    if (warp >= N) return;
    float4 acc = agg_node(bias, warp, lane);
    __half2 lo = __floats2half2_rn(acc.x, acc.y);
    __half2 hi = __floats2half2_rn(acc.z, acc.w);
    *(uint2*)(g_h1 + (size_t)warp * D + lane * 4) =
        make_uint2(*(unsigned*)&lo, *(unsigned*)&hi);
}

// layer 3: fused global mean-pool (sum via atomics; div later)
__global__ void __launch_bounds__(256)
k_agg_pool(const float* __restrict__ bias, const int* __restrict__ batch,
           float* __restrict__ out, int N) {
    int warp = (blockIdx.x * blockDim.x + threadIdx.x) >> 5;
    int lane = threadIdx.x & 31;
    if (warp >= N) return;
    float4 acc = agg_node(bias, warp, lane);
    int g = batch[warp];
    float* o = out + (size_t)g * D + lane * 4;
    atomicAdd(o + 0, acc.x);
    atomicAdd(o + 1, acc.y);
    atomicAdd(o + 2, acc.z);
    atomicAdd(o + 3, acc.w);
}

__global__ void k_div(float* __restrict__ out) {
    int i = blockIdx.x * blockDim.x + threadIdx.x;
    if (i < NGRAPH * D) out[i] = out[i] / fmaxf(g_gcnt[i >> 7], 1.f);
}

// ---------------------------------------------------------------------------
extern "C" void kernel_launch(void* const* d_in, const int* in_sizes, int n_in,
                              void* d_out, int out_size) {
    const float* x  = (const float*)d_in[0];
    // d_in[1] = edge_attr (unused)
    const float* W1 = (const float*)d_in[2];
    const float* b1 = (const float*)d_in[3];
    const float* W2 = (const float*)d_in[4];
    const float* b2 = (const float*)d_in[5];
    const float* W3 = (const float*)d_in[6];
    const float* b3 = (const float*)d_in[7];
    const int* ei    = (const int*)d_in[8];
    const int* batch = (const int*)d_in[9];
    float* out = (float*)d_out;

    int N = in_sizes[0] / D;
    int E = in_sizes[8] / 2;
    const int* src = ei;
    const int* dst = ei + E;

    int span = N > NGRAPH * D ? N : NGRAPH * D;
    int initb = (span + 255) / 256;
    int eb = (E + 255) / 256;
    int gb = (N + 127) / 128;
    int ab = ((N * 32) + 255) / 256;
    int sb = (N + SCAN_ELEMS - 1) / SCAN_ELEMS;

    // preprocessing
    k_init<<<initb, 256>>>(out, N);
    k_wconv<<<dim3(16, 3), 256>>>(W1, W2, W3);
    k_count<<<eb, 256>>>(dst, E);
    k_scan1<<<sb, SCAN_T>>>(batch, N);
    k_scan2<<<1, 32>>>(sb, N);
    k_scan3<<<sb, SCAN_T>>>(N);
    k_fill<<<eb, 256>>>(src, dst, E);

    // layer 1: x -> h1
    k_gemm<<<gb, 256>>>(x, 0, N, 1);
    k_agg<<<ab, 256>>>(b1, N);
    // layer 2: h1 -> h1
    k_gemm<<<gb, 256>>>(x, 1, N, 0);
    k_agg<<<ab, 256>>>(b2, N);
    // layer 3: h1 -> out (fused pool)
    k_gemm<<<gb, 256>>>(x, 2, N, 0);
    k_agg_pool<<<ab, 256>>>(b3, batch, out, N);

    k_div<<<(NGRAPH * D + 255) / 256, 256>>>(out);
}